// round 3
// baseline (speedup 1.0000x reference)
#include <cuda_runtime.h>

#define BB 4
#define TT 4096
#define CC 1024
#define HS 64
#define SCALE 0.03125f   // CC^-0.5 = 1/32 (reference scales by n_embd, not head_size)

// Scratch for q,k,v projections: [B,T,HS] fp32 each (4 MB each, static __device__)
__device__ float g_q[BB * TT * HS];
__device__ float g_k[BB * TT * HS];
__device__ float g_v[BB * TT * HS];

// ---------------------------------------------------------------------------
// Kernel 1: QKV projection.  out = x @ W + b  for W in {Wq,Wk,Wv} (blockIdx.y)
// Block tile: 128 rows x 64 cols, 256 threads (16x16), microtile 8x4, KB=32.
// ---------------------------------------------------------------------------
#define PM  128
#define PKB 32

__global__ __launch_bounds__(256) void qkv_kernel(
    const float* __restrict__ x,
    const float* __restrict__ Wq, const float* __restrict__ bq,
    const float* __restrict__ Wk, const float* __restrict__ bk,
    const float* __restrict__ Wv, const float* __restrict__ bv)
{
    __shared__ float xs[PKB][PM + 1];   // transposed x tile, pad 129 -> conflict-free STS
    __shared__ float ws[PKB][HS];       // W tile, natural

    const float* W;  const float* bias;  float* outp;
    if (blockIdx.y == 0)      { W = Wq; bias = bq; outp = g_q; }
    else if (blockIdx.y == 1) { W = Wk; bias = bk; outp = g_k; }
    else                      { W = Wv; bias = bv; outp = g_v; }

    const int m0  = blockIdx.x * PM;
    const int tid = threadIdx.x;
    const int ty  = tid >> 4;      // 0..15 -> 8-row group
    const int tx  = tid & 15;      // 0..15 -> 4-col group

    float acc[8][4];
    #pragma unroll
    for (int r = 0; r < 8; r++)
        #pragma unroll
        for (int c = 0; c < 4; c++) acc[r][c] = 0.f;

    for (int k0 = 0; k0 < CC; k0 += PKB) {
        // load x chunk [128 x 32], coalesced read, transposed store
        #pragma unroll
        for (int i = tid; i < PM * PKB; i += 256) {
            int m = i >> 5, kk = i & 31;
            xs[kk][m] = x[(size_t)(m0 + m) * CC + k0 + kk];
        }
        // load W chunk [32 x 64], natural
        #pragma unroll
        for (int i = tid; i < PKB * HS; i += 256) {
            int kk = i >> 6, n = i & 63;
            ws[kk][n] = W[(size_t)(k0 + kk) * HS + n];
        }
        __syncthreads();

        #pragma unroll
        for (int kk = 0; kk < PKB; kk++) {
            float4 wv = *(const float4*)&ws[kk][tx * 4];
            #pragma unroll
            for (int r = 0; r < 8; r++) {
                float xv = xs[kk][ty * 8 + r];
                acc[r][0] += xv * wv.x;
                acc[r][1] += xv * wv.y;
                acc[r][2] += xv * wv.z;
                acc[r][3] += xv * wv.w;
            }
        }
        __syncthreads();
    }

    const float b0 = bias[tx * 4 + 0];
    const float b1 = bias[tx * 4 + 1];
    const float b2 = bias[tx * 4 + 2];
    const float b3 = bias[tx * 4 + 3];
    #pragma unroll
    for (int r = 0; r < 8; r++) {
        float4 o;
        o.x = acc[r][0] + b0;
        o.y = acc[r][1] + b1;
        o.z = acc[r][2] + b2;
        o.w = acc[r][3] + b3;
        *(float4*)&outp[(size_t)(m0 + ty * 8 + r) * HS + tx * 4] = o;
    }
}

// ---------------------------------------------------------------------------
// Kernel 2: flash-style causal attention, fp32.
// CTA = 2 paired q-tiles (i and 63-i) of 64 queries each -> constant work.
// 256 threads (16x16), 4x4 microtile for both S=Q*K^T and O += P*V.
// Smem: Qs[d][m] (pad 65, scalar broadcast reads)
//       Ks[d][n] (pad 68, float4 reads; reused as Ps[m][n] after S phase)
//       Vs[n][h] (natural, float4 reads)
// ---------------------------------------------------------------------------
#define AM 64
#define QS_STRIDE 65
#define KS_STRIDE 68
#define ATTN_SMEM_FLOATS (AM * QS_STRIDE + AM * KS_STRIDE + AM * HS)
#define ATTN_SMEM_BYTES  (ATTN_SMEM_FLOATS * 4)

__global__ __launch_bounds__(256) void attn_kernel(float* __restrict__ out)
{
    extern __shared__ float smem[];
    float* Qs = smem;                       // [64][65]
    float* Ks = Qs + AM * QS_STRIDE;        // [64][68]  (also Ps)
    float* Vs = Ks + AM * KS_STRIDE;        // [64][64]

    const int b    = blockIdx.y;
    const int pair = blockIdx.x;            // 0..31
    const int tid  = threadIdx.x;
    const int ty   = tid >> 4;              // row group (4 rows)
    const int tx   = tid & 15;              // col group (4 cols)

    const float* qb = g_q + (size_t)b * TT * HS;
    const float* kb = g_k + (size_t)b * TT * HS;
    const float* vb = g_v + (size_t)b * TT * HS;
    float*       ob = out + (size_t)b * TT * HS;

    for (int half = 0; half < 2; half++) {
        const int qi = half ? (TT / AM - 1 - pair) : pair;
        const int m0 = qi * AM;

        __syncthreads();
        // load Q tile transposed: Qs[d][m]
        #pragma unroll
        for (int i = tid; i < AM * HS; i += 256) {
            int m = i >> 6, d = i & 63;
            Qs[d * QS_STRIDE + m] = qb[(size_t)(m0 + m) * HS + d];
        }

        float mr[4], lr[4], o[4][4];
        #pragma unroll
        for (int r = 0; r < 4; r++) {
            mr[r] = -1e30f; lr[r] = 0.f;
            #pragma unroll
            for (int c = 0; c < 4; c++) o[r][c] = 0.f;
        }

        for (int j = 0; j <= qi; j++) {
            const int n0 = j * AM;
            __syncthreads();   // prev PV done (and Q load visible on j==0)
            // load K tile transposed: Ks[d][n]; V tile natural: Vs[n][h]
            #pragma unroll
            for (int i = tid; i < AM * HS; i += 256) {
                int n = i >> 6, d = i & 63;
                Ks[d * KS_STRIDE + n] = kb[(size_t)(n0 + n) * HS + d];
            }
            #pragma unroll
            for (int i = tid; i < AM * HS; i += 256) {
                int n = i >> 6, h = i & 63;
                Vs[n * HS + h] = vb[(size_t)(n0 + n) * HS + h];
            }
            __syncthreads();

            // ---- S = Q * K^T (4x4 microtile) ----
            float s[4][4];
            #pragma unroll
            for (int r = 0; r < 4; r++)
                #pragma unroll
                for (int c = 0; c < 4; c++) s[r][c] = 0.f;

            #pragma unroll 8
            for (int d = 0; d < HS; d++) {
                float4 kv = *(const float4*)&Ks[d * KS_STRIDE + tx * 4];
                #pragma unroll
                for (int r = 0; r < 4; r++) {
                    float qv = Qs[d * QS_STRIDE + ty * 4 + r];
                    s[r][0] += qv * kv.x;
                    s[r][1] += qv * kv.y;
                    s[r][2] += qv * kv.z;
                    s[r][3] += qv * kv.w;
                }
            }

            // ---- scale + causal mask (only diagonal tile needs masking) ----
            if (j == qi) {
                #pragma unroll
                for (int r = 0; r < 4; r++)
                    #pragma unroll
                    for (int c = 0; c < 4; c++)
                        s[r][c] = (tx * 4 + c <= ty * 4 + r) ? s[r][c] * SCALE : -1e30f;
            } else {
                #pragma unroll
                for (int r = 0; r < 4; r++)
                    #pragma unroll
                    for (int c = 0; c < 4; c++)
                        s[r][c] *= SCALE;
            }

            // ---- online softmax (row reduction over tx = lane bits 0..3) ----
            #pragma unroll
            for (int r = 0; r < 4; r++) {
                float tm = fmaxf(fmaxf(s[r][0], s[r][1]), fmaxf(s[r][2], s[r][3]));
                tm = fmaxf(tm, __shfl_xor_sync(0xffffffffu, tm, 1));
                tm = fmaxf(tm, __shfl_xor_sync(0xffffffffu, tm, 2));
                tm = fmaxf(tm, __shfl_xor_sync(0xffffffffu, tm, 4));
                tm = fmaxf(tm, __shfl_xor_sync(0xffffffffu, tm, 8));
                float mn = fmaxf(mr[r], tm);
                float al = __expf(mr[r] - mn);
                mr[r] = mn;
                float rs = 0.f;
                #pragma unroll
                for (int c = 0; c < 4; c++) {
                    s[r][c] = __expf(s[r][c] - mn);
                    rs += s[r][c];
                }
                rs += __shfl_xor_sync(0xffffffffu, rs, 1);
                rs += __shfl_xor_sync(0xffffffffu, rs, 2);
                rs += __shfl_xor_sync(0xffffffffu, rs, 4);
                rs += __shfl_xor_sync(0xffffffffu, rs, 8);
                lr[r] = lr[r] * al + rs;
                #pragma unroll
                for (int c = 0; c < 4; c++) o[r][c] *= al;
            }

            __syncthreads();   // all threads done reading Ks before P overwrite
            // write P into the K buffer: Ps[m][n], float4 rows
            #pragma unroll
            for (int r = 0; r < 4; r++)
                *(float4*)&Ks[(ty * 4 + r) * KS_STRIDE + tx * 4] =
                    make_float4(s[r][0], s[r][1], s[r][2], s[r][3]);
            __syncthreads();

            // ---- O += P * V ----
            #pragma unroll 8
            for (int n = 0; n < AM; n++) {
                float4 vv = *(const float4*)&Vs[n * HS + tx * 4];
                #pragma unroll
                for (int r = 0; r < 4; r++) {
                    float pv = Ks[(ty * 4 + r) * KS_STRIDE + n];
                    o[r][0] += pv * vv.x;
                    o[r][1] += pv * vv.y;
                    o[r][2] += pv * vv.z;
                    o[r][3] += pv * vv.w;
                }
            }
        }

        // ---- epilogue: O / l -> out ----
        #pragma unroll
        for (int r = 0; r < 4; r++) {
            float inv = 1.0f / lr[r];
            float4 o4 = make_float4(o[r][0] * inv, o[r][1] * inv,
                                    o[r][2] * inv, o[r][3] * inv);
            *(float4*)&ob[(size_t)(m0 + ty * 4 + r) * HS + tx * 4] = o4;
        }
    }
}

// ---------------------------------------------------------------------------
extern "C" void kernel_launch(void* const* d_in, const int* in_sizes, int n_in,
                              void* d_out, int out_size)
{
    const float* x  = (const float*)d_in[0];
    const float* Wq = (const float*)d_in[1];
    const float* bq = (const float*)d_in[2];
    const float* Wk = (const float*)d_in[3];
    const float* bk = (const float*)d_in[4];
    const float* Wv = (const float*)d_in[5];
    const float* bv = (const float*)d_in[6];
    float* out = (float*)d_out;

    // >48KB dynamic smem opt-in (idempotent; non-stream API, capture-safe)
    (void)cudaFuncSetAttribute(attn_kernel,
                               cudaFuncAttributeMaxDynamicSharedMemorySize,
                               ATTN_SMEM_BYTES);

    qkv_kernel<<<dim3((BB * TT) / PM, 3), 256>>>(x, Wq, bq, Wk, bk, Wv, bv);
    attn_kernel<<<dim3(TT / AM / 2, BB), 256, ATTN_SMEM_BYTES>>>(out);
}

// round 5
// speedup vs baseline: 2.3009x; 2.3009x over previous
#include <cuda_runtime.h>
#include <cuda_bf16.h>
#include <cstdint>

#define BB 4
#define TT 4096
#define CC 1024
#define HS 64
#define SCALE 0.03125f   // CC^-0.5 = 1/32 (reference scales by n_embd, not head_size)

// Scratch for q,k,v projections: [B,T,HS] fp32 each
__device__ float g_q[BB * TT * HS];
__device__ float g_k[BB * TT * HS];
__device__ float g_v[BB * TT * HS];

// ===========================================================================
// mma.sync / ldmatrix helpers (base PTX, legal on plain sm_100)
// ===========================================================================
__device__ __forceinline__ uint32_t smem_u32(const void* p) {
    uint32_t a;
    asm("{ .reg .u64 t; cvta.to.shared.u64 t, %1; cvt.u32.u64 %0, t; }"
        : "=r"(a) : "l"(p));
    return a;
}

__device__ __forceinline__ void ldsm4(uint32_t* r, uint32_t a) {
    asm volatile("ldmatrix.sync.aligned.m8n8.x4.shared.b16 {%0,%1,%2,%3}, [%4];"
        : "=r"(r[0]), "=r"(r[1]), "=r"(r[2]), "=r"(r[3]) : "r"(a));
}
__device__ __forceinline__ void ldsm4t(uint32_t* r, uint32_t a) {
    asm volatile("ldmatrix.sync.aligned.m8n8.x4.trans.shared.b16 {%0,%1,%2,%3}, [%4];"
        : "=r"(r[0]), "=r"(r[1]), "=r"(r[2]), "=r"(r[3]) : "r"(a));
}
// D += A*B, m16n8k16 bf16, fp32 accum (in-place)
__device__ __forceinline__ void mma16816(float* d, const uint32_t* a, const uint32_t* b) {
    asm volatile(
        "mma.sync.aligned.m16n8k16.row.col.f32.bf16.bf16.f32 "
        "{%0,%1,%2,%3}, {%4,%5,%6,%7}, {%8,%9}, {%0,%1,%2,%3};"
        : "+f"(d[0]), "+f"(d[1]), "+f"(d[2]), "+f"(d[3])
        : "r"(a[0]), "r"(a[1]), "r"(a[2]), "r"(a[3]), "r"(b[0]), "r"(b[1]));
}

__device__ __forceinline__ uint32_t pk2(float x, float y) {
    __nv_bfloat162 t = __floats2bfloat162_rn(x, y);
    return *reinterpret_cast<uint32_t*>(&t);
}
__device__ __forceinline__ float bhi(float x) {
    return __bfloat162float(__float2bfloat16_rn(x));
}

// All bf16 tiles: row-major, 64 cols = 128B rows, 16B chunks swizzled chunk^=(row&7)
// A-operand x4 (non-trans): tiles (m-lo,k-lo),(m-hi,k-lo),(m-lo,k-hi),(m-hi,k-hi)
__device__ __forceinline__ uint32_t a_addr(uint32_t base, int lane, int mbase, int cbase) {
    int t = lane >> 3, r = lane & 7;
    int row = mbase + ((t & 1) << 3) + r;
    int chunk = cbase + (t >> 1);
    return base + row * 128 + (((chunk ^ (row & 7))) << 4);
}
// B from K-style storage [n][k] (non-trans): tiles (nt,kh0),(nt,kh1),(nt+1,kh0),(nt+1,kh1)
__device__ __forceinline__ uint32_t bk_addr(uint32_t base, int lane, int nbase, int cbase) {
    int t = lane >> 3, r = lane & 7;
    int row = nbase + ((t >> 1) << 3) + r;
    int chunk = cbase + (t & 1);
    return base + row * 128 + (((chunk ^ (row & 7))) << 4);
}
// B from V-style storage [k][n] (.trans): k-chunk pair, fixed n-chunk
__device__ __forceinline__ uint32_t bv_addr(uint32_t base, int lane, int krow0, int chunk) {
    int t = lane >> 3, r = lane & 7;
    int row = krow0 + ((t >> 1) << 4) + ((t & 1) << 3) + r;
    return base + row * 128 + (((chunk ^ (row & 7))) << 4);
}
// B from W-style storage [k][n] (.trans): fixed k-chunk, n-tile pair
__device__ __forceinline__ uint32_t bw_addr(uint32_t base, int lane, int krow0, int ntchunk0) {
    int t = lane >> 3, r = lane & 7;
    int row = krow0 + ((t & 1) << 3) + r;
    int chunk = ntchunk0 + (t >> 1);
    return base + row * 128 + (((chunk ^ (row & 7))) << 4);
}

// split fp32 float4 -> hi/lo bf16x4 (8B each) and store at swizzled offset
__device__ __forceinline__ void split_store(char* hi_b, char* lo_b, int row, int q4, float4 v) {
    uint32_t off = (uint32_t)(row * 128 + ((((q4 >> 1) ^ (row & 7))) << 4) + ((q4 & 1) << 3));
    uint2 h, l;
    h.x = pk2(v.x, v.y); h.y = pk2(v.z, v.w);
    l.x = pk2(v.x - bhi(v.x), v.y - bhi(v.y));
    l.y = pk2(v.z - bhi(v.z), v.w - bhi(v.w));
    *(uint2*)(hi_b + off) = h;
    *(uint2*)(lo_b + off) = l;
}

// ===========================================================================
// Kernel 1: QKV projection via mma.sync bf16 3-product split.
// CTA: M=64 rows, N=192 (3 weights x 64), K=1024 in 16 stages of 64.
// Warp w: rows 16*(w&3), cols 96*(w>>2) (12 n-tiles of 8).
// ===========================================================================
#define QKV_SMEM_BYTES (8192 * 2 + 24576 * 2 + 768)

__global__ __launch_bounds__(256) void qkv_mma(
    const float* __restrict__ x,
    const float* __restrict__ Wq, const float* __restrict__ bq,
    const float* __restrict__ Wk, const float* __restrict__ bk,
    const float* __restrict__ Wv, const float* __restrict__ bv)
{
    extern __shared__ char sm[];
    char* xhi = sm;                 // [64][64] bf16 swz
    char* xlo = sm + 8192;
    char* whi = sm + 16384;         // 3 x [64][64] bf16 swz
    char* wlo = sm + 40960;
    float* bias_s = (float*)(sm + 65536);   // 192 floats

    const uint32_t xhi_u = smem_u32(xhi), xlo_u = smem_u32(xlo);
    const uint32_t whi_u = smem_u32(whi), wlo_u = smem_u32(wlo);

    const int tid  = threadIdx.x;
    const int wid  = tid >> 5;
    const int lane = tid & 31;
    const int tg   = lane & 3;
    const int g    = lane >> 2;
    const int m0   = blockIdx.x * 64;
    const int wm   = 16 * (wid & 3);
    const int wn   = wid >> 2;      // n-half: 96 cols each

    if (tid < 192) {
        const float* bp = (tid < 64) ? bq : ((tid < 128) ? bk : bv);
        bias_s[tid] = bp[tid & 63];
    }

    float acc[12][4];
    #pragma unroll
    for (int i = 0; i < 12; i++)
        #pragma unroll
        for (int c = 0; c < 4; c++) acc[i][c] = 0.f;

    for (int kb = 0; kb < 16; kb++) {
        const int k0 = kb * 64;
        __syncthreads();
        #pragma unroll
        for (int i = 0; i < 4; i++) {
            int f = tid + i * 256;
            int row = f >> 4, q4 = f & 15;
            float4 v = *(const float4*)(x + (size_t)(m0 + row) * CC + k0 + q4 * 4);
            split_store(xhi, xlo, row, q4, v);
        }
        #pragma unroll
        for (int ws = 0; ws < 3; ws++) {
            const float* Wp = (ws == 0) ? Wq : ((ws == 1) ? Wk : Wv);
            #pragma unroll
            for (int i = 0; i < 4; i++) {
                int f = tid + i * 256;
                int kr = f >> 4, q4 = f & 15;
                float4 v = *(const float4*)(Wp + (size_t)(k0 + kr) * HS + q4 * 4);
                split_store(whi + ws * 8192, wlo + ws * 8192, kr, q4, v);
            }
        }
        __syncthreads();

        #pragma unroll
        for (int kc = 0; kc < 4; kc++) {
            uint32_t ah[4], al4[4];
            ldsm4(ah,  a_addr(xhi_u, lane, wm, kc * 2));
            ldsm4(al4, a_addr(xlo_u, lane, wm, kc * 2));
            #pragma unroll
            for (int ntp = 0; ntp < 6; ntp++) {
                int gnt  = 12 * wn + 2 * ntp;
                int wsel = gnt >> 3;
                int lnt  = gnt & 7;
                uint32_t bh[4], bl[4];
                ldsm4t(bh, bw_addr(whi_u + wsel * 8192, lane, kc * 16, lnt));
                ldsm4t(bl, bw_addr(wlo_u + wsel * 8192, lane, kc * 16, lnt));
                #pragma unroll
                for (int i = 0; i < 2; i++) {
                    int ln = 2 * ntp + i;
                    mma16816(acc[ln], ah,  &bh[2 * i]);
                    mma16816(acc[ln], ah,  &bl[2 * i]);
                    mma16816(acc[ln], al4, &bh[2 * i]);
                }
            }
        }
    }

    #pragma unroll
    for (int ln = 0; ln < 12; ln++) {
        int gnt  = 12 * wn + ln;
        int wsel = gnt >> 3;
        int col  = (gnt & 7) * 8 + 2 * tg;
        float* op = (wsel == 0) ? g_q : ((wsel == 1) ? g_k : g_v);
        float b0 = bias_s[wsel * 64 + col];
        float b1 = bias_s[wsel * 64 + col + 1];
        float2 o0 = make_float2(acc[ln][0] + b0, acc[ln][1] + b1);
        float2 o1 = make_float2(acc[ln][2] + b0, acc[ln][3] + b1);
        *(float2*)(op + (size_t)(m0 + wm + g)     * HS + col) = o0;
        *(float2*)(op + (size_t)(m0 + wm + g + 8) * HS + col) = o1;
    }
}

// ===========================================================================
// Kernel 2: flash attention, mma.sync bf16 3-product for S and PV,
// SIMT fp32 online softmax (R3-proven) in between.
// CTA = 2 paired q-tiles of 64; warp w: rows 16*(w&3), col-half 32*(w>>2).
// ===========================================================================
#define AQHI 0
#define AQLO 8192
#define AKHI 16384
#define AKLO 24576
#define AVHI 32768
#define AVLO 40960
#define APHI 49152
#define APLO 57344
#define ASS  65536                  // [64][68] fp32
#define AALR 82944                  // alpha[64]
#define ALLR 83200                  // l[64]
#define ATTN_SMEM_BYTES 83456
#define SSTR 68

__global__ __launch_bounds__(256) void attn_mma(float* __restrict__ out)
{
    extern __shared__ char sm[];
    char*  Qhi = sm + AQHI; char* Qlo = sm + AQLO;
    char*  Khi = sm + AKHI; char* Klo = sm + AKLO;
    char*  Vhi = sm + AVHI; char* Vlo = sm + AVLO;
    char*  Phi = sm + APHI; char* Plo = sm + APLO;
    float* Ss  = (float*)(sm + ASS);
    float* al_arr = (float*)(sm + AALR);
    float* l_arr  = (float*)(sm + ALLR);

    const uint32_t Qhi_u = smem_u32(Qhi), Qlo_u = smem_u32(Qlo);
    const uint32_t Khi_u = smem_u32(Khi), Klo_u = smem_u32(Klo);
    const uint32_t Vhi_u = smem_u32(Vhi), Vlo_u = smem_u32(Vlo);
    const uint32_t Phi_u = smem_u32(Phi), Plo_u = smem_u32(Plo);

    const int tid  = threadIdx.x;
    const int wid  = tid >> 5;
    const int lane = tid & 31;
    const int g    = lane >> 2;
    const int tg   = lane & 3;
    const int wm   = 16 * (wid & 3);   // warp row base
    const int wn   = wid >> 2;         // warp col half (0/1)
    const int ty   = tid >> 4;         // softmax row group (4 rows)
    const int tx   = tid & 15;         // softmax col group (4 cols)

    const int b    = blockIdx.y;
    const int pair = blockIdx.x;       // 0..31

    const float* qb = g_q + (size_t)b * TT * HS;
    const float* kb = g_k + (size_t)b * TT * HS;
    const float* vb = g_v + (size_t)b * TT * HS;
    float*       ob = out + (size_t)b * TT * HS;

    for (int half = 0; half < 2; half++) {
        const int qtile = half ? (TT / 64 - 1 - pair) : pair;
        const int m0 = qtile * 64;

        __syncthreads();
        #pragma unroll
        for (int i = 0; i < 4; i++) {
            int f = tid + i * 256;
            int row = f >> 4, q4 = f & 15;
            float4 v = *(const float4*)(qb + (size_t)(m0 + row) * HS + q4 * 4);
            split_store(Qhi, Qlo, row, q4, v);
        }
        __syncthreads();

        uint32_t qh[4][4], ql[4][4];
        #pragma unroll
        for (int kc = 0; kc < 4; kc++) {
            ldsm4(qh[kc], a_addr(Qhi_u, lane, wm, kc * 2));
            ldsm4(ql[kc], a_addr(Qlo_u, lane, wm, kc * 2));
        }

        float mr[4], lr[4];
        #pragma unroll
        for (int r = 0; r < 4; r++) { mr[r] = -1e30f; lr[r] = 0.f; }
        float o[4][4];
        #pragma unroll
        for (int h = 0; h < 4; h++)
            #pragma unroll
            for (int c = 0; c < 4; c++) o[h][c] = 0.f;

        for (int j = 0; j <= qtile; j++) {
            const int n0 = j * 64;
            __syncthreads();   // prev PV done reading V/P; K free
            #pragma unroll
            for (int i = 0; i < 4; i++) {
                int f = tid + i * 256;
                int row = f >> 4, q4 = f & 15;
                float4 v = *(const float4*)(kb + (size_t)(n0 + row) * HS + q4 * 4);
                split_store(Khi, Klo, row, q4, v);
            }
            #pragma unroll
            for (int i = 0; i < 4; i++) {
                int f = tid + i * 256;
                int row = f >> 4, q4 = f & 15;
                float4 v = *(const float4*)(vb + (size_t)(n0 + row) * HS + q4 * 4);
                split_store(Vhi, Vlo, row, q4, v);
            }
            __syncthreads();

            // ---- S = Q K^T : warp computes 16 x 32 ----
            float sfr[4][4];
            #pragma unroll
            for (int nt = 0; nt < 4; nt++)
                #pragma unroll
                for (int c = 0; c < 4; c++) sfr[nt][c] = 0.f;

            #pragma unroll
            for (int kc = 0; kc < 4; kc++) {
                #pragma unroll
                for (int ntp = 0; ntp < 2; ntp++) {
                    uint32_t kh[4], kl4[4];
                    int nbase = 32 * wn + 16 * ntp;
                    ldsm4(kh,  bk_addr(Khi_u, lane, nbase, kc * 2));
                    ldsm4(kl4, bk_addr(Klo_u, lane, nbase, kc * 2));
                    #pragma unroll
                    for (int i = 0; i < 2; i++) {
                        int nt = 2 * ntp + i;
                        mma16816(sfr[nt], qh[kc], &kh[2 * i]);
                        mma16816(sfr[nt], qh[kc], &kl4[2 * i]);
                        mma16816(sfr[nt], ql[kc], &kh[2 * i]);
                    }
                }
            }

            #pragma unroll
            for (int nt = 0; nt < 4; nt++) {
                int col = 32 * wn + nt * 8 + 2 * tg;
                *(float2*)&Ss[(wm + g)     * SSTR + col] = make_float2(sfr[nt][0], sfr[nt][1]);
                *(float2*)&Ss[(wm + g + 8) * SSTR + col] = make_float2(sfr[nt][2], sfr[nt][3]);
            }
            __syncthreads();

            // ---- SIMT online softmax ----
            {
                float s[4][4];
                #pragma unroll
                for (int r = 0; r < 4; r++) {
                    float4 t4 = *(float4*)&Ss[(ty * 4 + r) * SSTR + tx * 4];
                    s[r][0] = t4.x; s[r][1] = t4.y; s[r][2] = t4.z; s[r][3] = t4.w;
                }
                if (j == qtile) {
                    #pragma unroll
                    for (int r = 0; r < 4; r++)
                        #pragma unroll
                        for (int c = 0; c < 4; c++)
                            s[r][c] = (tx * 4 + c <= ty * 4 + r) ? s[r][c] * SCALE : -1e30f;
                } else {
                    #pragma unroll
                    for (int r = 0; r < 4; r++)
                        #pragma unroll
                        for (int c = 0; c < 4; c++)
                            s[r][c] *= SCALE;
                }
                #pragma unroll
                for (int r = 0; r < 4; r++) {
                    float tm = fmaxf(fmaxf(s[r][0], s[r][1]), fmaxf(s[r][2], s[r][3]));
                    tm = fmaxf(tm, __shfl_xor_sync(0xffffffffu, tm, 1));
                    tm = fmaxf(tm, __shfl_xor_sync(0xffffffffu, tm, 2));
                    tm = fmaxf(tm, __shfl_xor_sync(0xffffffffu, tm, 4));
                    tm = fmaxf(tm, __shfl_xor_sync(0xffffffffu, tm, 8));
                    float mn = fmaxf(mr[r], tm);
                    float al = __expf(mr[r] - mn);
                    mr[r] = mn;
                    float rs = 0.f;
                    #pragma unroll
                    for (int c = 0; c < 4; c++) {
                        s[r][c] = __expf(s[r][c] - mn);
                        rs += s[r][c];
                    }
                    rs += __shfl_xor_sync(0xffffffffu, rs, 1);
                    rs += __shfl_xor_sync(0xffffffffu, rs, 2);
                    rs += __shfl_xor_sync(0xffffffffu, rs, 4);
                    rs += __shfl_xor_sync(0xffffffffu, rs, 8);
                    lr[r] = lr[r] * al + rs;
                    if (tx == 0) al_arr[ty * 4 + r] = al;
                    int prow = ty * 4 + r;
                    uint32_t off = (uint32_t)(prow * 128 +
                        ((((tx >> 1) ^ (prow & 7))) << 4) + ((tx & 1) << 3));
                    uint2 hv, lv;
                    hv.x = pk2(s[r][0], s[r][1]); hv.y = pk2(s[r][2], s[r][3]);
                    lv.x = pk2(s[r][0] - bhi(s[r][0]), s[r][1] - bhi(s[r][1]));
                    lv.y = pk2(s[r][2] - bhi(s[r][2]), s[r][3] - bhi(s[r][3]));
                    *(uint2*)(Phi + off) = hv;
                    *(uint2*)(Plo + off) = lv;
                }
            }
            __syncthreads();

            // ---- O = alpha*O + P V ----
            {
                float a0 = al_arr[wm + g];
                float a1 = al_arr[wm + g + 8];
                #pragma unroll
                for (int h = 0; h < 4; h++) {
                    o[h][0] *= a0; o[h][1] *= a0;
                    o[h][2] *= a1; o[h][3] *= a1;
                }
                #pragma unroll
                for (int ncp = 0; ncp < 2; ncp++) {
                    uint32_t ph[2][4], pl[2][4];
                    #pragma unroll
                    for (int i = 0; i < 2; i++) {
                        int nc = 2 * ncp + i;
                        ldsm4(ph[i], a_addr(Phi_u, lane, wm, nc * 2));
                        ldsm4(pl[i], a_addr(Plo_u, lane, wm, nc * 2));
                    }
                    #pragma unroll
                    for (int ht = 0; ht < 4; ht++) {
                        uint32_t vh[4], vl[4];
                        int chunk = 4 * wn + ht;
                        ldsm4t(vh, bv_addr(Vhi_u, lane, ncp * 32, chunk));
                        ldsm4t(vl, bv_addr(Vlo_u, lane, ncp * 32, chunk));
                        #pragma unroll
                        for (int i = 0; i < 2; i++) {
                            mma16816(o[ht], ph[i], &vh[2 * i]);
                            mma16816(o[ht], ph[i], &vl[2 * i]);
                            mma16816(o[ht], pl[i], &vh[2 * i]);
                        }
                    }
                }
            }
        }

        if (tx == 0) {
            #pragma unroll
            for (int r = 0; r < 4; r++) l_arr[ty * 4 + r] = lr[r];
        }
        __syncthreads();
        {
            float inv0 = 1.0f / l_arr[wm + g];
            float inv1 = 1.0f / l_arr[wm + g + 8];
            #pragma unroll
            for (int ht = 0; ht < 4; ht++) {
                int col = 32 * wn + ht * 8 + 2 * tg;
                float2 o0 = make_float2(o[ht][0] * inv0, o[ht][1] * inv0);
                float2 o1 = make_float2(o[ht][2] * inv1, o[ht][3] * inv1);
                *(float2*)(ob + (size_t)(m0 + wm + g)     * HS + col) = o0;
                *(float2*)(ob + (size_t)(m0 + wm + g + 8) * HS + col) = o1;
            }
        }
    }
}

// ---------------------------------------------------------------------------
extern "C" void kernel_launch(void* const* d_in, const int* in_sizes, int n_in,
                              void* d_out, int out_size)
{
    const float* x  = (const float*)d_in[0];
    const float* Wq = (const float*)d_in[1];
    const float* bq = (const float*)d_in[2];
    const float* Wk = (const float*)d_in[3];
    const float* bk = (const float*)d_in[4];
    const float* Wv = (const float*)d_in[5];
    const float* bv = (const float*)d_in[6];
    float* out = (float*)d_out;

    (void)cudaFuncSetAttribute(qkv_mma,
                               cudaFuncAttributeMaxDynamicSharedMemorySize,
                               QKV_SMEM_BYTES);
    (void)cudaFuncSetAttribute(attn_mma,
                               cudaFuncAttributeMaxDynamicSharedMemorySize,
                               ATTN_SMEM_BYTES);

    qkv_mma<<<(BB * TT) / 64, 256, QKV_SMEM_BYTES>>>(x, Wq, bq, Wk, bk, Wv, bv);
    attn_mma<<<dim3(TT / 64 / 2, BB), 256, ATTN_SMEM_BYTES>>>(out);
}

// round 6
// speedup vs baseline: 2.7555x; 1.1976x over previous
#include <cuda_runtime.h>
#include <cuda_bf16.h>
#include <cstdint>

#define BB 4
#define TT 4096
#define CC 1024
#define HS 64
#define SCALE 0.03125f   // CC^-0.5 = 1/32 (reference scales by n_embd, not head_size)

// Scratch for q,k,v projections: [B,T,HS] fp32 each
__device__ float g_q[BB * TT * HS];
__device__ float g_k[BB * TT * HS];
__device__ float g_v[BB * TT * HS];

// ===========================================================================
// mma.sync / ldmatrix helpers (base PTX, legal on plain sm_100)
// ===========================================================================
__device__ __forceinline__ uint32_t smem_u32(const void* p) {
    uint32_t a;
    asm("{ .reg .u64 t; cvta.to.shared.u64 t, %1; cvt.u32.u64 %0, t; }"
        : "=r"(a) : "l"(p));
    return a;
}

__device__ __forceinline__ void ldsm4(uint32_t* r, uint32_t a) {
    asm volatile("ldmatrix.sync.aligned.m8n8.x4.shared.b16 {%0,%1,%2,%3}, [%4];"
        : "=r"(r[0]), "=r"(r[1]), "=r"(r[2]), "=r"(r[3]) : "r"(a));
}
__device__ __forceinline__ void ldsm4t(uint32_t* r, uint32_t a) {
    asm volatile("ldmatrix.sync.aligned.m8n8.x4.trans.shared.b16 {%0,%1,%2,%3}, [%4];"
        : "=r"(r[0]), "=r"(r[1]), "=r"(r[2]), "=r"(r[3]) : "r"(a));
}
// D += A*B, m16n8k16 bf16, fp32 accum (in-place)
__device__ __forceinline__ void mma16816(float* d, const uint32_t* a, const uint32_t* b) {
    asm volatile(
        "mma.sync.aligned.m16n8k16.row.col.f32.bf16.bf16.f32 "
        "{%0,%1,%2,%3}, {%4,%5,%6,%7}, {%8,%9}, {%0,%1,%2,%3};"
        : "+f"(d[0]), "+f"(d[1]), "+f"(d[2]), "+f"(d[3])
        : "r"(a[0]), "r"(a[1]), "r"(a[2]), "r"(a[3]), "r"(b[0]), "r"(b[1]));
}

__device__ __forceinline__ uint32_t pk2(float x, float y) {
    __nv_bfloat162 t = __floats2bfloat162_rn(x, y);
    return *reinterpret_cast<uint32_t*>(&t);
}
__device__ __forceinline__ float bhi(float x) {
    return __bfloat162float(__float2bfloat16_rn(x));
}

// All bf16 tiles: row-major, 64 cols = 128B rows, 16B chunks swizzled chunk^=(row&7)
// A-operand x4 (non-trans)
__device__ __forceinline__ uint32_t a_addr(uint32_t base, int lane, int mbase, int cbase) {
    int t = lane >> 3, r = lane & 7;
    int row = mbase + ((t & 1) << 3) + r;
    int chunk = cbase + (t >> 1);
    return base + row * 128 + (((chunk ^ (row & 7))) << 4);
}
// B from K-style storage [n][k] (non-trans): 2 n-tiles x k16
__device__ __forceinline__ uint32_t bk_addr(uint32_t base, int lane, int nbase, int cbase) {
    int t = lane >> 3, r = lane & 7;
    int row = nbase + ((t >> 1) << 3) + r;
    int chunk = cbase + (t & 1);
    return base + row * 128 + (((chunk ^ (row & 7))) << 4);
}
// B from V-style storage [k][n] (.trans): k32 x one 8-col chunk
__device__ __forceinline__ uint32_t bv_addr(uint32_t base, int lane, int krow0, int chunk) {
    int t = lane >> 3, r = lane & 7;
    int row = krow0 + ((t >> 1) << 4) + ((t & 1) << 3) + r;
    return base + row * 128 + (((chunk ^ (row & 7))) << 4);
}
// B from W-style storage [k][n] (.trans): fixed k16, 2 n-tiles
__device__ __forceinline__ uint32_t bw_addr(uint32_t base, int lane, int krow0, int ntchunk0) {
    int t = lane >> 3, r = lane & 7;
    int row = krow0 + ((t & 1) << 3) + r;
    int chunk = ntchunk0 + (t >> 1);
    return base + row * 128 + (((chunk ^ (row & 7))) << 4);
}

// split fp32 float4 -> hi/lo bf16x4 (8B each) and store at swizzled offset
__device__ __forceinline__ void split_store(char* hi_b, char* lo_b, int row, int q4, float4 v) {
    uint32_t off = (uint32_t)(row * 128 + ((((q4 >> 1) ^ (row & 7))) << 4) + ((q4 & 1) << 3));
    uint2 h, l;
    h.x = pk2(v.x, v.y); h.y = pk2(v.z, v.w);
    l.x = pk2(v.x - bhi(v.x), v.y - bhi(v.y));
    l.y = pk2(v.z - bhi(v.z), v.w - bhi(v.w));
    *(uint2*)(hi_b + off) = h;
    *(uint2*)(lo_b + off) = l;
}

// ===========================================================================
// Kernel 1: QKV projection, mma.sync bf16 3-product, register-prefetch
// double buffer (2 smem stages, 1 sync/stage).
// CTA: M=64 rows, N=192, K=1024 in 16 stages of 64.
// ===========================================================================
// per-stage layout: xhi 0, xlo 8192, whi 16384(3x8192), wlo 40960(3x8192)
#define QKV_STAGE 65536
#define QKV_SMEM_BYTES (2 * QKV_STAGE + 768)

__global__ __launch_bounds__(256) void qkv_mma(
    const float* __restrict__ x,
    const float* __restrict__ Wq, const float* __restrict__ bq,
    const float* __restrict__ Wk, const float* __restrict__ bk,
    const float* __restrict__ Wv, const float* __restrict__ bv)
{
    extern __shared__ char sm[];
    float* bias_s = (float*)(sm + 2 * QKV_STAGE);

    const uint32_t sm_u = smem_u32(sm);
    const int tid  = threadIdx.x;
    const int wid  = tid >> 5;
    const int lane = tid & 31;
    const int tg   = lane & 3;
    const int g    = lane >> 2;
    const int m0   = blockIdx.x * 64;
    const int wm   = 16 * (wid & 3);
    const int wn   = wid >> 2;

    if (tid < 192) {
        const float* bp = (tid < 64) ? bq : ((tid < 128) ? bk : bv);
        bias_s[tid] = bp[tid & 63];
    }

    // prefetch registers
    float4 xr[4], wr[3][4];
    const int xrow = tid >> 4, xq4 = tid & 15;   // fixed per thread (f = tid + i*256)
    // x rows: tid>>4 + i*16 ; W rows: same pattern
    {
        const int k0 = 0;
        #pragma unroll
        for (int i = 0; i < 4; i++)
            xr[i] = *(const float4*)(x + (size_t)(m0 + xrow + i * 16) * CC + k0 + xq4 * 4);
        #pragma unroll
        for (int ws = 0; ws < 3; ws++) {
            const float* Wp = (ws == 0) ? Wq : ((ws == 1) ? Wk : Wv);
            #pragma unroll
            for (int i = 0; i < 4; i++)
                wr[ws][i] = *(const float4*)(Wp + (size_t)(k0 + xrow + i * 16) * HS + xq4 * 4);
        }
    }

    float acc[12][4];
    #pragma unroll
    for (int i = 0; i < 12; i++)
        #pragma unroll
        for (int c = 0; c < 4; c++) acc[i][c] = 0.f;

    for (int kb = 0; kb < 16; kb++) {
        const int st = kb & 1;
        char* base = sm + st * QKV_STAGE;
        const uint32_t base_u = sm_u + st * QKV_STAGE;

        // store prefetched regs -> smem (split bf16)
        #pragma unroll
        for (int i = 0; i < 4; i++)
            split_store(base, base + 8192, xrow + i * 16, xq4, xr[i]);
        #pragma unroll
        for (int ws = 0; ws < 3; ws++)
            #pragma unroll
            for (int i = 0; i < 4; i++)
                split_store(base + 16384 + ws * 8192, base + 40960 + ws * 8192,
                            xrow + i * 16, xq4, wr[ws][i]);
        __syncthreads();

        // prefetch next stage (latency overlapped with mma below)
        if (kb < 15) {
            const int k0 = (kb + 1) * 64;
            #pragma unroll
            for (int i = 0; i < 4; i++)
                xr[i] = *(const float4*)(x + (size_t)(m0 + xrow + i * 16) * CC + k0 + xq4 * 4);
            #pragma unroll
            for (int ws = 0; ws < 3; ws++) {
                const float* Wp = (ws == 0) ? Wq : ((ws == 1) ? Wk : Wv);
                #pragma unroll
                for (int i = 0; i < 4; i++)
                    wr[ws][i] = *(const float4*)(Wp + (size_t)(k0 + xrow + i * 16) * HS + xq4 * 4);
            }
        }

        const uint32_t xhi_u = base_u, xlo_u = base_u + 8192;
        const uint32_t whi_u = base_u + 16384, wlo_u = base_u + 40960;
        #pragma unroll
        for (int kc = 0; kc < 4; kc++) {
            uint32_t ah[4], al4[4];
            ldsm4(ah,  a_addr(xhi_u, lane, wm, kc * 2));
            ldsm4(al4, a_addr(xlo_u, lane, wm, kc * 2));
            #pragma unroll
            for (int ntp = 0; ntp < 6; ntp++) {
                int gnt  = 12 * wn + 2 * ntp;
                int wsel = gnt >> 3;
                int lnt  = gnt & 7;
                uint32_t bh[4], bl[4];
                ldsm4t(bh, bw_addr(whi_u + wsel * 8192, lane, kc * 16, lnt));
                ldsm4t(bl, bw_addr(wlo_u + wsel * 8192, lane, kc * 16, lnt));
                #pragma unroll
                for (int i = 0; i < 2; i++) {
                    int ln = 2 * ntp + i;
                    mma16816(acc[ln], ah,  &bh[2 * i]);
                    mma16816(acc[ln], ah,  &bl[2 * i]);
                    mma16816(acc[ln], al4, &bh[2 * i]);
                }
            }
        }
        // no trailing sync needed: next store targets the other stage, and the
        // store->sync of this iteration proves all warps finished the previous
        // stage's mma before anyone overwrites it.
    }

    #pragma unroll
    for (int ln = 0; ln < 12; ln++) {
        int gnt  = 12 * wn + ln;
        int wsel = gnt >> 3;
        int col  = (gnt & 7) * 8 + 2 * tg;
        float* op = (wsel == 0) ? g_q : ((wsel == 1) ? g_k : g_v);
        float b0 = bias_s[wsel * 64 + col];
        float b1 = bias_s[wsel * 64 + col + 1];
        float2 o0 = make_float2(acc[ln][0] + b0, acc[ln][1] + b1);
        float2 o1 = make_float2(acc[ln][2] + b0, acc[ln][3] + b1);
        *(float2*)(op + (size_t)(m0 + wm + g)     * HS + col) = o0;
        *(float2*)(op + (size_t)(m0 + wm + g + 8) * HS + col) = o1;
    }
}

// ===========================================================================
// Kernel 2: flash attention, warp-specialized.
// Warps 0-3: compute (warp owns 16 rows x 64 cols; fragment-resident softmax;
//            P repacked accum->A-frags in registers, no smem roundtrip).
// Warps 4-7: producers (double-buffered K/V load+split).
// 1 __syncthreads per key tile.
// ===========================================================================
// smem: Qhi 0, Qlo 8192; buf s at 16384+s*32768: Khi+0 Klo+8192 Vhi+16384 Vlo+24576
#define ATTN_SMEM_BYTES (16384 + 2 * 32768)

__global__ __launch_bounds__(256) void attn_mma(float* __restrict__ out)
{
    extern __shared__ char sm[];
    const uint32_t sm_u = smem_u32(sm);

    const int tid  = threadIdx.x;
    const int wid  = tid >> 5;
    const int lane = tid & 31;
    const int g    = lane >> 2;
    const int tg   = lane & 3;
    const bool consumer = (wid < 4);
    const int wm   = 16 * wid;          // consumer row base (wid 0..3)
    const int ptid = tid & 127;         // producer-local tid

    const int b    = blockIdx.y;
    const int pair = blockIdx.x;        // 0..31

    const float* qb = g_q + (size_t)b * TT * HS;
    const float* kb = g_k + (size_t)b * TT * HS;
    const float* vb = g_v + (size_t)b * TT * HS;
    float*       ob = out + (size_t)b * TT * HS;

    for (int half = 0; half < 2; half++) {
        const int qtile = half ? (TT / 64 - 1 - pair) : pair;
        const int m0 = qtile * 64;

        __syncthreads();   // all reads of Q/K/V buffers from previous half done

        if (consumer) {
            // consumers load Q tile (128 threads, 8 float4 each)
            #pragma unroll
            for (int i = 0; i < 8; i++) {
                int f = ptid + i * 128;
                int row = f >> 4, q4 = f & 15;
                float4 v = *(const float4*)(qb + (size_t)(m0 + row) * HS + q4 * 4);
                split_store(sm, sm + 8192, row, q4, v);
            }
        } else {
            // producers prefill buf 0 with K/V tile j=0
            char* kbase = sm + 16384;
            #pragma unroll
            for (int i = 0; i < 8; i++) {
                int f = ptid + i * 128;
                int row = f >> 4, q4 = f & 15;
                float4 kv4 = *(const float4*)(kb + (size_t)row * HS + q4 * 4);
                float4 vv4 = *(const float4*)(vb + (size_t)row * HS + q4 * 4);
                split_store(kbase,         kbase + 8192,  row, q4, kv4);
                split_store(kbase + 16384, kbase + 24576, row, q4, vv4);
            }
        }
        __syncthreads();

        // consumer state
        uint32_t qh[4][4], ql[4][4];
        float o[8][4];
        float mr0 = -1e30f, mr1 = -1e30f, lr0 = 0.f, lr1 = 0.f;
        if (consumer) {
            #pragma unroll
            for (int kc = 0; kc < 4; kc++) {
                ldsm4(qh[kc], a_addr(sm_u,        lane, wm, kc * 2));
                ldsm4(ql[kc], a_addr(sm_u + 8192, lane, wm, kc * 2));
            }
            #pragma unroll
            for (int ct = 0; ct < 8; ct++)
                #pragma unroll
                for (int c = 0; c < 4; c++) o[ct][c] = 0.f;
        }

        for (int j = 0; j <= qtile; j++) {
            const int s = j & 1;

            if (!consumer) {
                // fill next buffer while consumers compute current
                if (j < qtile) {
                    const int n0n = (j + 1) * 64;
                    char* kbase = sm + 16384 + ((j + 1) & 1) * 32768;
                    #pragma unroll
                    for (int i = 0; i < 8; i++) {
                        int f = ptid + i * 128;
                        int row = f >> 4, q4 = f & 15;
                        float4 kv4 = *(const float4*)(kb + (size_t)(n0n + row) * HS + q4 * 4);
                        float4 vv4 = *(const float4*)(vb + (size_t)(n0n + row) * HS + q4 * 4);
                        split_store(kbase,         kbase + 8192,  row, q4, kv4);
                        split_store(kbase + 16384, kbase + 24576, row, q4, vv4);
                    }
                }
            } else {
                const uint32_t kbu = sm_u + 16384 + s * 32768;
                const uint32_t Khi_u = kbu, Klo_u = kbu + 8192;
                const uint32_t Vhi_u = kbu + 16384, Vlo_u = kbu + 24576;

                // ---- S = Q K^T : 16 rows x 64 cols per warp ----
                float sa[8][4];
                #pragma unroll
                for (int nt = 0; nt < 8; nt++)
                    #pragma unroll
                    for (int c = 0; c < 4; c++) sa[nt][c] = 0.f;

                #pragma unroll
                for (int kc = 0; kc < 4; kc++) {
                    #pragma unroll
                    for (int ntp = 0; ntp < 4; ntp++) {
                        uint32_t kh[4], kl4[4];
                        ldsm4(kh,  bk_addr(Khi_u, lane, 16 * ntp, kc * 2));
                        ldsm4(kl4, bk_addr(Klo_u, lane, 16 * ntp, kc * 2));
                        #pragma unroll
                        for (int i = 0; i < 2; i++) {
                            int nt = 2 * ntp + i;
                            mma16816(sa[nt], qh[kc], &kh[2 * i]);
                            mma16816(sa[nt], qh[kc], &kl4[2 * i]);
                            mma16816(sa[nt], ql[kc], &kh[2 * i]);
                        }
                    }
                }

                // ---- scale + causal mask ----
                if (j == qtile) {
                    #pragma unroll
                    for (int nt = 0; nt < 8; nt++) {
                        int c0 = nt * 8 + 2 * tg;
                        sa[nt][0] = (c0     <= wm + g)     ? sa[nt][0] * SCALE : -1e30f;
                        sa[nt][1] = (c0 + 1 <= wm + g)     ? sa[nt][1] * SCALE : -1e30f;
                        sa[nt][2] = (c0     <= wm + g + 8) ? sa[nt][2] * SCALE : -1e30f;
                        sa[nt][3] = (c0 + 1 <= wm + g + 8) ? sa[nt][3] * SCALE : -1e30f;
                    }
                } else {
                    #pragma unroll
                    for (int nt = 0; nt < 8; nt++)
                        #pragma unroll
                        for (int c = 0; c < 4; c++) sa[nt][c] *= SCALE;
                }

                // ---- fragment-resident online softmax ----
                float tm0 = -1e30f, tm1 = -1e30f;
                #pragma unroll
                for (int nt = 0; nt < 8; nt++) {
                    tm0 = fmaxf(tm0, fmaxf(sa[nt][0], sa[nt][1]));
                    tm1 = fmaxf(tm1, fmaxf(sa[nt][2], sa[nt][3]));
                }
                tm0 = fmaxf(tm0, __shfl_xor_sync(0xffffffffu, tm0, 1));
                tm0 = fmaxf(tm0, __shfl_xor_sync(0xffffffffu, tm0, 2));
                tm1 = fmaxf(tm1, __shfl_xor_sync(0xffffffffu, tm1, 1));
                tm1 = fmaxf(tm1, __shfl_xor_sync(0xffffffffu, tm1, 2));
                float mn0 = fmaxf(mr0, tm0), mn1 = fmaxf(mr1, tm1);
                float al0 = __expf(mr0 - mn0), al1 = __expf(mr1 - mn1);
                mr0 = mn0; mr1 = mn1;
                float rs0 = 0.f, rs1 = 0.f;
                #pragma unroll
                for (int nt = 0; nt < 8; nt++) {
                    sa[nt][0] = __expf(sa[nt][0] - mn0);
                    sa[nt][1] = __expf(sa[nt][1] - mn0);
                    sa[nt][2] = __expf(sa[nt][2] - mn1);
                    sa[nt][3] = __expf(sa[nt][3] - mn1);
                    rs0 += sa[nt][0] + sa[nt][1];
                    rs1 += sa[nt][2] + sa[nt][3];
                }
                rs0 += __shfl_xor_sync(0xffffffffu, rs0, 1);
                rs0 += __shfl_xor_sync(0xffffffffu, rs0, 2);
                rs1 += __shfl_xor_sync(0xffffffffu, rs1, 1);
                rs1 += __shfl_xor_sync(0xffffffffu, rs1, 2);
                lr0 = lr0 * al0 + rs0;
                lr1 = lr1 * al1 + rs1;
                #pragma unroll
                for (int ct = 0; ct < 8; ct++) {
                    o[ct][0] *= al0; o[ct][1] *= al0;
                    o[ct][2] *= al1; o[ct][3] *= al1;
                }

                // ---- O += P V ; P repacked accum->A-frags in registers ----
                #pragma unroll
                for (int kp = 0; kp < 2; kp++) {      // 32-key groups
                    uint32_t ph[2][4], pl[2][4];
                    #pragma unroll
                    for (int i = 0; i < 2; i++) {     // k16 halves
                        int t0 = 4 * kp + 2 * i;      // n-tile pair for this k16
                        ph[i][0] = pk2(sa[t0][0], sa[t0][1]);
                        ph[i][1] = pk2(sa[t0][2], sa[t0][3]);
                        ph[i][2] = pk2(sa[t0 + 1][0], sa[t0 + 1][1]);
                        ph[i][3] = pk2(sa[t0 + 1][2], sa[t0 + 1][3]);
                        pl[i][0] = pk2(sa[t0][0] - bhi(sa[t0][0]), sa[t0][1] - bhi(sa[t0][1]));
                        pl[i][1] = pk2(sa[t0][2] - bhi(sa[t0][2]), sa[t0][3] - bhi(sa[t0][3]));
                        pl[i][2] = pk2(sa[t0 + 1][0] - bhi(sa[t0 + 1][0]), sa[t0 + 1][1] - bhi(sa[t0 + 1][1]));
                        pl[i][3] = pk2(sa[t0 + 1][2] - bhi(sa[t0 + 1][2]), sa[t0 + 1][3] - bhi(sa[t0 + 1][3]));
                    }
                    #pragma unroll
                    for (int ct = 0; ct < 8; ct++) {
                        uint32_t vh[4], vl[4];
                        ldsm4t(vh, bv_addr(Vhi_u, lane, kp * 32, ct));
                        ldsm4t(vl, bv_addr(Vlo_u, lane, kp * 32, ct));
                        #pragma unroll
                        for (int i = 0; i < 2; i++) {
                            mma16816(o[ct], ph[i], &vh[2 * i]);
                            mma16816(o[ct], ph[i], &vl[2 * i]);
                            mma16816(o[ct], pl[i], &vh[2 * i]);
                        }
                    }
                }
            }
            __syncthreads();
        }

        // ---- epilogue ----
        if (consumer) {
            float inv0 = 1.0f / lr0, inv1 = 1.0f / lr1;
            #pragma unroll
            for (int ct = 0; ct < 8; ct++) {
                int col = ct * 8 + 2 * tg;
                float2 o0 = make_float2(o[ct][0] * inv0, o[ct][1] * inv0);
                float2 o1 = make_float2(o[ct][2] * inv1, o[ct][3] * inv1);
                *(float2*)(ob + (size_t)(m0 + wm + g)     * HS + col) = o0;
                *(float2*)(ob + (size_t)(m0 + wm + g + 8) * HS + col) = o1;
            }
        }
    }
}

// ---------------------------------------------------------------------------
extern "C" void kernel_launch(void* const* d_in, const int* in_sizes, int n_in,
                              void* d_out, int out_size)
{
    const float* x  = (const float*)d_in[0];
    const float* Wq = (const float*)d_in[1];
    const float* bq = (const float*)d_in[2];
    const float* Wk = (const float*)d_in[3];
    const float* bk = (const float*)d_in[4];
    const float* Wv = (const float*)d_in[5];
    const float* bv = (const float*)d_in[6];
    float* out = (float*)d_out;

    (void)cudaFuncSetAttribute(qkv_mma,
                               cudaFuncAttributeMaxDynamicSharedMemorySize,
                               QKV_SMEM_BYTES);
    (void)cudaFuncSetAttribute(attn_mma,
                               cudaFuncAttributeMaxDynamicSharedMemorySize,
                               ATTN_SMEM_BYTES);

    qkv_mma<<<(BB * TT) / 64, 256, QKV_SMEM_BYTES>>>(x, Wq, bq, Wk, bk, Wv, bv);
    attn_mma<<<dim3(TT / 64 / 2, BB), 256, ATTN_SMEM_BYTES>>>(out);
}